// round 9
// baseline (speedup 1.0000x reference)
#include <cuda_runtime.h>
#include <math.h>

// ---------------- problem constants ----------------
#define T_TOK 4096
#define DM    512
#define DFF   2048
#define DN    128
#define DH    256
#define TK    64
#define EPSV  1e-5f

// ---------------- scratch (device globals, no allocation) ----------------
__device__ float g_lnx[T_TOK * DM];
__device__ float g_h[T_TOK * DM];
__device__ float g_scores[T_TOK * DFF];
__device__ int   g_idx[T_TOK * TK];
__device__ float g_agg[T_TOK * DH];
__device__ float g_rln[T_TOK * DH];
__device__ float g_r[T_TOK * DM];

__device__ __forceinline__ float gelu_f(float x) {
    return 0.5f * x * (1.0f + erff(x * 0.7071067811865476f));
}
__device__ __forceinline__ float to_tf32(float x) {
    float y; asm("cvt.rna.tf32.f32 %0, %1;" : "=f"(y) : "f"(x)); return y;
}
__device__ __forceinline__ void mma_tf32(float* c, const unsigned* a, const unsigned* b) {
    asm volatile("mma.sync.aligned.m16n8k8.row.col.f32.tf32.tf32.f32 "
                 "{%0,%1,%2,%3}, {%4,%5,%6,%7}, {%8,%9}, {%0,%1,%2,%3};"
                 : "+f"(c[0]), "+f"(c[1]), "+f"(c[2]), "+f"(c[3])
                 : "r"(a[0]), "r"(a[1]), "r"(a[2]), "r"(a[3]),
                   "r"(b[0]), "r"(b[1]));
}

// ---------------- LayerNorm over last dim (D = 256 or 512), block per row ----
__global__ void ln_kernel(const float* __restrict__ in, const float* __restrict__ g,
                          const float* __restrict__ b, float* __restrict__ out, int D) {
    int t = blockIdx.x, tid = threadIdx.x;
    int lane = tid & 31, wid = tid >> 5;
    __shared__ float red[8];
    __shared__ float s_mu, s_rs;
    const float* row = in + (size_t)t * D;
    float v0 = row[tid];
    float v1 = (D > 256) ? row[tid + 256] : 0.0f;
    float sum = v0 + v1;
    #pragma unroll
    for (int o = 16; o; o >>= 1) sum += __shfl_xor_sync(0xffffffffu, sum, o);
    if (lane == 0) red[wid] = sum;
    __syncthreads();
    if (tid == 0) {
        float s = 0.f;
        #pragma unroll
        for (int w = 0; w < 8; w++) s += red[w];
        s_mu = s / (float)D;
    }
    __syncthreads();
    float mu = s_mu;
    float d0 = v0 - mu, d1 = (D > 256) ? (v1 - mu) : 0.0f;
    float vs = d0 * d0 + d1 * d1;
    #pragma unroll
    for (int o = 16; o; o >>= 1) vs += __shfl_xor_sync(0xffffffffu, vs, o);
    if (lane == 0) red[wid] = vs;
    __syncthreads();
    if (tid == 0) {
        float s = 0.f;
        #pragma unroll
        for (int w = 0; w < 8; w++) s += red[w];
        s_rs = rsqrtf(s / (float)D + EPSV);
    }
    __syncthreads();
    float rs = s_rs;
    float* orow = out + (size_t)t * D;
    orow[tid] = d0 * rs * g[tid] + b[tid];
    if (D > 256) orow[tid + 256] = d1 * rs * g[tid + 256] + b[tid + 256];
}

// ---------------- scalar fp32 GEMM, 128x128 tile, 8x8/thread -----------------
// Exact fp32: single accumulator per output, fmaf over strictly ascending k.
#define SBM 128
#define SBN 128
#define SBK 16
#define SAT 132
#define SBT 132
template <int B_LAYOUT, bool HAS_BIAS, bool DO_GELU>
__global__ void __launch_bounds__(256, 2)
gemm_f32big(const float* __restrict__ A, const float* __restrict__ B,
            const float* __restrict__ bias, float* __restrict__ C,
            int M, int N, int K) {
    __shared__ float As[SBK * SAT];
    __shared__ float Bs[SBK * SBT];
    const int tid = threadIdx.x;
    const int tx = tid & 15, ty = tid >> 4;
    const int m0 = blockIdx.y * SBM, n0 = blockIdx.x * SBN;
    float acc[8][8] = {};
    for (int k0 = 0; k0 < K; k0 += SBK) {
        __syncthreads();
        {
            int r = tid >> 1, kh = (tid & 1) * 8;
            const float* src = A + (size_t)(m0 + r) * K + k0 + kh;
            float4 v0 = *reinterpret_cast<const float4*>(src);
            float4 v1 = *reinterpret_cast<const float4*>(src + 4);
            float f[8] = {v0.x, v0.y, v0.z, v0.w, v1.x, v1.y, v1.z, v1.w};
            #pragma unroll
            for (int j = 0; j < 8; j++) As[(kh + j) * SAT + r] = f[j];
        }
        if (B_LAYOUT == 1) {
            int n = tid >> 1, kh = (tid & 1) * 8;
            const float* src = B + (size_t)(n0 + n) * K + k0 + kh;
            float4 v0 = *reinterpret_cast<const float4*>(src);
            float4 v1 = *reinterpret_cast<const float4*>(src + 4);
            float f[8] = {v0.x, v0.y, v0.z, v0.w, v1.x, v1.y, v1.z, v1.w};
            #pragma unroll
            for (int j = 0; j < 8; j++) Bs[(kh + j) * SBT + n] = f[j];
        } else {
            int kr = tid >> 4, nn = (tid & 15) * 8;
            const float* src = B + (size_t)(k0 + kr) * N + n0 + nn;
            float4 v0 = *reinterpret_cast<const float4*>(src);
            float4 v1 = *reinterpret_cast<const float4*>(src + 4);
            Bs[kr * SBT + nn + 0] = v0.x; Bs[kr * SBT + nn + 1] = v0.y;
            Bs[kr * SBT + nn + 2] = v0.z; Bs[kr * SBT + nn + 3] = v0.w;
            Bs[kr * SBT + nn + 4] = v1.x; Bs[kr * SBT + nn + 5] = v1.y;
            Bs[kr * SBT + nn + 6] = v1.z; Bs[kr * SBT + nn + 7] = v1.w;
        }
        __syncthreads();
        #pragma unroll 4
        for (int kc = 0; kc < SBK; kc++) {
            float a[8], b[8];
            float4 a0 = *reinterpret_cast<const float4*>(&As[kc * SAT + ty * 8]);
            float4 a1 = *reinterpret_cast<const float4*>(&As[kc * SAT + ty * 8 + 4]);
            float4 b0 = *reinterpret_cast<const float4*>(&Bs[kc * SBT + tx * 8]);
            float4 b1 = *reinterpret_cast<const float4*>(&Bs[kc * SBT + tx * 8 + 4]);
            a[0] = a0.x; a[1] = a0.y; a[2] = a0.z; a[3] = a0.w;
            a[4] = a1.x; a[5] = a1.y; a[6] = a1.z; a[7] = a1.w;
            b[0] = b0.x; b[1] = b0.y; b[2] = b0.z; b[3] = b0.w;
            b[4] = b1.x; b[5] = b1.y; b[6] = b1.z; b[7] = b1.w;
            #pragma unroll
            for (int i = 0; i < 8; i++)
                #pragma unroll
                for (int j = 0; j < 8; j++)
                    acc[i][j] = fmaf(a[i], b[j], acc[i][j]);
        }
    }
    #pragma unroll
    for (int i = 0; i < 8; i++) {
        int m = m0 + ty * 8 + i;
        float v[8];
        #pragma unroll
        for (int j = 0; j < 8; j++) {
            v[j] = acc[i][j];
            if (HAS_BIAS) v[j] += bias[n0 + tx * 8 + j];
            if (DO_GELU) v[j] = gelu_f(v[j]);
        }
        *reinterpret_cast<float4*>(&C[(size_t)m * N + n0 + tx * 8]) =
            make_float4(v[0], v[1], v[2], v[3]);
        *reinterpret_cast<float4*>(&C[(size_t)m * N + n0 + tx * 8 + 4]) =
            make_float4(v[4], v[5], v[6], v[7]);
    }
}

// ---------------- top-64 of 2048 via 4-pass byte radix select ----------------
__global__ void topk_kernel(const float* __restrict__ scores, int* __restrict__ idx) {
    __shared__ unsigned u_s[DFF];
    __shared__ int hist[256];
    __shared__ int cum[256];
    __shared__ unsigned s_prefix;
    __shared__ int s_krem, s_cnt, s_eqcnt;
    __shared__ int eq_idx[64];
    int t = blockIdx.x, tid = threadIdx.x;
    for (int i = tid; i < DFF; i += 256) {
        unsigned b = __float_as_uint(scores[(size_t)t * DFF + i]);
        b ^= ((unsigned)((int)b >> 31)) | 0x80000000u;
        u_s[i] = b;
    }
    if (tid == 0) { s_prefix = 0u; s_krem = TK; s_cnt = 0; s_eqcnt = 0; }
    __syncthreads();
    for (int shift = 24; shift >= 0; shift -= 8) {
        hist[tid] = 0;
        __syncthreads();
        unsigned pmask = (shift == 24) ? 0u : (0xFFFFFFFFu << (shift + 8));
        unsigned prefix = s_prefix;
        for (int i = tid; i < DFF; i += 256) {
            unsigned b = u_s[i];
            if ((b & pmask) == prefix) atomicAdd(&hist[(b >> shift) & 255], 1);
        }
        __syncthreads();
        cum[tid] = hist[tid];
        __syncthreads();
        #pragma unroll
        for (int off = 1; off < 256; off <<= 1) {
            int v = (tid + off < 256) ? cum[tid + off] : 0;
            __syncthreads();
            cum[tid] += v;
            __syncthreads();
        }
        int krem = s_krem;
        int above = (tid + 1 < 256) ? cum[tid + 1] : 0;
        if (cum[tid] >= krem && above < krem) {
            s_prefix = prefix | ((unsigned)tid << shift);
            s_krem = krem - above;
        }
        __syncthreads();
    }
    unsigned thr = s_prefix;
    int need_eq = s_krem;
    for (int i = tid; i < DFF; i += 256) {
        unsigned b = u_s[i];
        if (b > thr) {
            int p = atomicAdd(&s_cnt, 1);
            idx[(size_t)t * TK + p] = i;
        } else if (b == thr) {
            int p = atomicAdd(&s_eqcnt, 1);
            if (p < 64) eq_idx[p] = i;
        }
    }
    __syncthreads();
    if (tid == 0) {
        int n = s_eqcnt; if (n > 64) n = 64;
        for (int a = 1; a < n; a++) {
            int key = eq_idx[a]; int p = a - 1;
            while (p >= 0 && eq_idx[p] > key) { eq_idx[p + 1] = eq_idx[p]; p--; }
            eq_idx[p + 1] = key;
        }
        int base = s_cnt;
        for (int j = 0; j < need_eq; j++) idx[(size_t)t * TK + base + j] = eq_idx[j];
    }
}

// ---------------- phi: round-2 kernel, ONLY change = 16-row weight staging ---
// one block (256 thr = 8 warps) per token; warps tiled 2(m) x 4(n) over [64,256]
#define SA  140
#define SH  268
#define SWS 264
__global__ void __launch_bounds__(256, 2)
phi_kernel(const float* __restrict__ x, const float* __restrict__ W_in,
           const float* __restrict__ nv, const int* __restrict__ idx,
           const float* __restrict__ pW1, const float* __restrict__ pb1,
           const float* __restrict__ pln1_g, const float* __restrict__ pln1_b,
           const float* __restrict__ pW2, const float* __restrict__ pb2,
           const float* __restrict__ pln2_g, const float* __restrict__ pln2_b,
           float* __restrict__ agg) {
    extern __shared__ float sm[];
    float* h_s   = sm;                    // 64*268; phi_in aliases front
    float* phi_s = sm;                    // 64*140 (dead once GEMM1 done)
    float* xf_s  = sm + 64 * SH;          // 512
    float* w_s   = xf_s + 512;            // 16*264 (16-row staging)
    float* agg_s = w_s + 16 * SWS;        // 256
    int*   idx_s = (int*)(agg_s + 256);   // 64

    const int t = blockIdx.x, tid = threadIdx.x;
    const int lane = tid & 31, wid = tid >> 5;
    const int g = lane >> 2, tig = lane & 3;
    const int wm = wid >> 2, wn = wid & 3;

    if (tid < TK) idx_s[tid] = idx[(size_t)t * TK + tid];
    for (int i = tid; i < DM; i += 256) xf_s[i] = x[(size_t)t * DM + i];
    agg_s[tid] = 0.0f;
    __syncthreads();

    // gather neuron vectors (pre-rounded tf32) into phi_in[:,0:128]
    for (int e = tid; e < TK * DN; e += 256) {
        int k = e >> 7, c = e & 127;
        phi_s[k * SA + c] = to_tf32(nv[(size_t)idx_s[k] * DN + c]);
    }
    if (tid < TK) {
        #pragma unroll
        for (int c = 129; c < 136; c++) phi_s[tid * SA + c] = 0.0f;  // K pad
    }
    // act[k] = gelu(xf . W_in[idx[k]]) -> phi_in[:,128]  (fp32 exact)
    #pragma unroll
    for (int kr = 0; kr < 8; kr++) {
        int k = wid * 8 + kr;
        const float* wr = W_in + (size_t)idx_s[k] * DM;
        float s = 0.f;
        #pragma unroll
        for (int c = 0; c < DM / 32; c++) s = fmaf(xf_s[lane + 32 * c], wr[lane + 32 * c], s);
        #pragma unroll
        for (int o = 16; o; o >>= 1) s += __shfl_xor_sync(0xffffffffu, s, o);
        if (lane == 0) phi_s[k * SA + 128] = to_tf32(gelu_f(s));
    }

    float acc[2][8][4];
    #pragma unroll
    for (int i = 0; i < 2; i++)
        #pragma unroll
        for (int j = 0; j < 8; j++)
            #pragma unroll
            for (int q = 0; q < 4; q++) acc[i][j][q] = 0.f;

    // ---- GEMM1: [64,129] @ pW1[129,256] ----
    // 8 stages of 16 k-rows (k=0..127), then one 8-row tail (k=128..135).
    for (int ks = 0; ks < 8; ks++) {
        int k0 = ks * 16;
        __syncthreads();
        {   // stage 16 rows of pW1 as tf32: r = tid>>4 (0..15), 16 cols/thread
            int r = tid >> 4, c0 = (tid & 15) * 16;
            const float* src = pW1 + (size_t)(k0 + r) * 256 + c0;
            #pragma unroll
            for (int h = 0; h < 4; h++) {
                float4 p = *reinterpret_cast<const float4*>(src + h * 4);
                w_s[r * SWS + c0 + h * 4 + 0] = to_tf32(p.x);
                w_s[r * SWS + c0 + h * 4 + 1] = to_tf32(p.y);
                w_s[r * SWS + c0 + h * 4 + 2] = to_tf32(p.z);
                w_s[r * SWS + c0 + h * 4 + 3] = to_tf32(p.w);
            }
        }
        __syncthreads();
        #pragma unroll
        for (int sub = 0; sub < 2; sub++) {
            int k = k0 + sub * 8;
            unsigned a[2][4];
            #pragma unroll
            for (int mt = 0; mt < 2; mt++) {
                const float* ap = phi_s + (size_t)(wm * 32 + mt * 16 + g) * SA + k + tig;
                a[mt][0] = __float_as_uint(ap[0]);
                a[mt][1] = __float_as_uint(ap[8 * SA]);
                a[mt][2] = __float_as_uint(ap[4]);
                a[mt][3] = __float_as_uint(ap[8 * SA + 4]);
            }
            #pragma unroll
            for (int nt = 0; nt < 8; nt++) {
                unsigned b[2];
                int ncol = wn * 64 + nt * 8 + g;
                b[0] = __float_as_uint(w_s[(sub * 8 + tig) * SWS + ncol]);
                b[1] = __float_as_uint(w_s[(sub * 8 + tig + 4) * SWS + ncol]);
                mma_tf32(acc[0][nt], a[0], b);
                mma_tf32(acc[1][nt], a[1], b);
            }
        }
    }
    {   // tail: k = 128..135 (row 128 real = act weights; 129..135 zero)
        __syncthreads();
        {   // stage 8 rows: r = tid>>5 (0..7), 8 cols/thread
            int r = tid >> 5, c0 = (tid & 31) * 8;
            float v[8];
            if (r == 0) {
                float4 p = *reinterpret_cast<const float4*>(pW1 + (size_t)128 * 256 + c0);
                float4 q = *reinterpret_cast<const float4*>(pW1 + (size_t)128 * 256 + c0 + 4);
                v[0] = p.x; v[1] = p.y; v[2] = p.z; v[3] = p.w;
                v[4] = q.x; v[5] = q.y; v[6] = q.z; v[7] = q.w;
            } else {
                #pragma unroll
                for (int i = 0; i < 8; i++) v[i] = 0.f;
            }
            #pragma unroll
            for (int i = 0; i < 8; i++) w_s[r * SWS + c0 + i] = to_tf32(v[i]);
        }
        __syncthreads();
        const int k = 128;
        unsigned a[2][4];
        #pragma unroll
        for (int mt = 0; mt < 2; mt++) {
            const float* ap = phi_s + (size_t)(wm * 32 + mt * 16 + g) * SA + k + tig;
            a[mt][0] = __float_as_uint(ap[0]);
            a[mt][1] = __float_as_uint(ap[8 * SA]);
            a[mt][2] = __float_as_uint(ap[4]);
            a[mt][3] = __float_as_uint(ap[8 * SA + 4]);
        }
        #pragma unroll
        for (int nt = 0; nt < 8; nt++) {
            unsigned b[2];
            int ncol = wn * 64 + nt * 8 + g;
            b[0] = __float_as_uint(w_s[tig * SWS + ncol]);
            b[1] = __float_as_uint(w_s[(tig + 4) * SWS + ncol]);
            mma_tf32(acc[0][nt], a[0], b);
            mma_tf32(acc[1][nt], a[1], b);
        }
    }
    __syncthreads();   // phi_s dead; safe to overwrite with h
    #pragma unroll
    for (int mt = 0; mt < 2; mt++) {
        int row = wm * 32 + mt * 16 + g;
        #pragma unroll
        for (int nt = 0; nt < 8; nt++) {
            int col = wn * 64 + nt * 8 + tig * 2;
            h_s[row * SH + col]           = acc[mt][nt][0];
            h_s[row * SH + col + 1]       = acc[mt][nt][1];
            h_s[(row + 8) * SH + col]     = acc[mt][nt][2];
            h_s[(row + 8) * SH + col + 1] = acc[mt][nt][3];
        }
    }
    __syncthreads();
    // ---- bias + LN1 + GELU (fp32), store back tf32 ----
    {
        float gg[8], bb[8], pb[8];
        #pragma unroll
        for (int q = 0; q < 8; q++) {
            int j = lane + 32 * q;
            gg[q] = pln1_g[j]; bb[q] = pln1_b[j]; pb[q] = pb1[j];
        }
        #pragma unroll
        for (int kr = 0; kr < 8; kr++) {
            int r = wid * 8 + kr;
            float v[8]; float sum = 0.f;
            #pragma unroll
            for (int q = 0; q < 8; q++) { v[q] = h_s[r * SH + lane + 32 * q] + pb[q]; sum += v[q]; }
            #pragma unroll
            for (int o = 16; o; o >>= 1) sum += __shfl_xor_sync(0xffffffffu, sum, o);
            float mu = sum * (1.f / 256.f);
            float vs = 0.f;
            #pragma unroll
            for (int q = 0; q < 8; q++) { float d = v[q] - mu; vs = fmaf(d, d, vs); }
            #pragma unroll
            for (int o = 16; o; o >>= 1) vs += __shfl_xor_sync(0xffffffffu, vs, o);
            float rs = rsqrtf(vs * (1.f / 256.f) + EPSV);
            #pragma unroll
            for (int q = 0; q < 8; q++)
                h_s[r * SH + lane + 32 * q] = to_tf32(gelu_f((v[q] - mu) * rs * gg[q] + bb[q]));
        }
    }

    // ---- GEMM2: [64,256] @ pW2[256,256], 16 stages of 16 k-rows ----
    #pragma unroll
    for (int i = 0; i < 2; i++)
        #pragma unroll
        for (int j = 0; j < 8; j++)
            #pragma unroll
            for (int q = 0; q < 4; q++) acc[i][j][q] = 0.f;
    for (int ks = 0; ks < 16; ks++) {
        int k0 = ks * 16;
        __syncthreads();
        {   // stage 16 rows of pW2 as tf32
            int r = tid >> 4, c0 = (tid & 15) * 16;
            const float* src = pW2 + (size_t)(k0 + r) * 256 + c0;
            #pragma unroll
            for (int h = 0; h < 4; h++) {
                float4 p = *reinterpret_cast<const float4*>(src + h * 4);
                w_s[r * SWS + c0 + h * 4 + 0] = to_tf32(p.x);
                w_s[r * SWS + c0 + h * 4 + 1] = to_tf32(p.y);
                w_s[r * SWS + c0 + h * 4 + 2] = to_tf32(p.z);
                w_s[r * SWS + c0 + h * 4 + 3] = to_tf32(p.w);
            }
        }
        __syncthreads();
        #pragma unroll
        for (int sub = 0; sub < 2; sub++) {
            int k = k0 + sub * 8;
            unsigned a[2][4];
            #pragma unroll
            for (int mt = 0; mt < 2; mt++) {
                const float* ap = h_s + (size_t)(wm * 32 + mt * 16 + g) * SH + k + tig;
                a[mt][0] = __float_as_uint(ap[0]);
                a[mt][1] = __float_as_uint(ap[8 * SH]);
                a[mt][2] = __float_as_uint(ap[4]);
                a[mt][3] = __float_as_uint(ap[8 * SH + 4]);
            }
            #pragma unroll
            for (int nt = 0; nt < 8; nt++) {
                unsigned b[2];
                int ncol = wn * 64 + nt * 8 + g;
                b[0] = __float_as_uint(w_s[(sub * 8 + tig) * SWS + ncol]);
                b[1] = __float_as_uint(w_s[(sub * 8 + tig + 4) * SWS + ncol]);
                mma_tf32(acc[0][nt], a[0], b);
                mma_tf32(acc[1][nt], a[1], b);
            }
        }
    }
    __syncthreads();
    #pragma unroll
    for (int mt = 0; mt < 2; mt++) {
        int row = wm * 32 + mt * 16 + g;
        #pragma unroll
        for (int nt = 0; nt < 8; nt++) {
            int col = wn * 64 + nt * 8 + tig * 2;
            h_s[row * SH + col]           = acc[mt][nt][0];
            h_s[row * SH + col + 1]       = acc[mt][nt][1];
            h_s[(row + 8) * SH + col]     = acc[mt][nt][2];
            h_s[(row + 8) * SH + col + 1] = acc[mt][nt][3];
        }
    }
    __syncthreads();
    // ---- bias + LN2 + sum over K ----
    {
        float gg[8], bb[8], pb[8], aw[8];
        #pragma unroll
        for (int q = 0; q < 8; q++) {
            int j = lane + 32 * q;
            gg[q] = pln2_g[j]; bb[q] = pln2_b[j]; pb[q] = pb2[j]; aw[q] = 0.f;
        }
        #pragma unroll
        for (int kr = 0; kr < 8; kr++) {
            int r = wid * 8 + kr;
            float v[8]; float sum = 0.f;
            #pragma unroll
            for (int q = 0; q < 8; q++) { v[q] = h_s[r * SH + lane + 32 * q] + pb[q]; sum += v[q]; }
            #pragma unroll
            for (int o = 16; o; o >>= 1) sum += __shfl_xor_sync(0xffffffffu, sum, o);
            float mu = sum * (1.f / 256.f);
            float vs = 0.f;
            #pragma unroll
            for (int q = 0; q < 8; q++) { float d = v[q] - mu; vs = fmaf(d, d, vs); }
            #pragma unroll
            for (int o = 16; o; o >>= 1) vs += __shfl_xor_sync(0xffffffffu, vs, o);
            float rs = rsqrtf(vs * (1.f / 256.f) + EPSV);
            #pragma unroll
            for (int q = 0; q < 8; q++)
                aw[q] += (v[q] - mu) * rs * gg[q] + bb[q];
        }
        #pragma unroll
        for (int q = 0; q < 8; q++) atomicAdd(&agg_s[lane + 32 * q], aw[q]);
    }
    __syncthreads();
    agg[(size_t)t * DH + tid] = agg_s[tid];
}

// ---------------- host launcher ----------------
extern "C" void kernel_launch(void* const* d_in, const int* in_sizes, int n_in,
                              void* d_out, int out_size) {
    const float* x      = (const float*)d_in[0];
    const float* W_in   = (const float*)d_in[1];
    const float* nv     = (const float*)d_in[2];
    const float* Wr1    = (const float*)d_in[3];
    const float* Wr2    = (const float*)d_in[4];
    const float* rn_g   = (const float*)d_in[5];
    const float* rn_b   = (const float*)d_in[6];
    const float* pW1    = (const float*)d_in[7];
    const float* pb1    = (const float*)d_in[8];
    const float* pln1_g = (const float*)d_in[9];
    const float* pln1_b = (const float*)d_in[10];
    const float* pW2    = (const float*)d_in[11];
    const float* pb2    = (const float*)d_in[12];
    const float* pln2_g = (const float*)d_in[13];
    const float* pln2_b = (const float*)d_in[14];
    const float* rln_g  = (const float*)d_in[15];
    const float* rln_b  = (const float*)d_in[16];
    const float* rW1    = (const float*)d_in[17];
    const float* rb1    = (const float*)d_in[18];
    const float* rW2    = (const float*)d_in[19];
    const float* rb2    = (const float*)d_in[20];
    float* out = (float*)d_out;

    float *p_lnx, *p_h, *p_scores, *p_agg, *p_rln, *p_r; int* p_idx;
    cudaGetSymbolAddress((void**)&p_lnx, g_lnx);
    cudaGetSymbolAddress((void**)&p_h, g_h);
    cudaGetSymbolAddress((void**)&p_scores, g_scores);
    cudaGetSymbolAddress((void**)&p_idx, g_idx);
    cudaGetSymbolAddress((void**)&p_agg, g_agg);
    cudaGetSymbolAddress((void**)&p_rln, g_rln);
    cudaGetSymbolAddress((void**)&p_r, g_r);

    const int PHI_SMEM = (64 * SH + 512 + 16 * SWS + 256) * 4 + TK * 4;
    cudaFuncSetAttribute(phi_kernel, cudaFuncAttributeMaxDynamicSharedMemorySize, PHI_SMEM);

    // 1. router LN (fp32 exact)
    ln_kernel<<<T_TOK, 256>>>(x, rn_g, rn_b, p_lnx, DM);
    // 2. h = gelu(ln_x @ Wr1^T)   — exact fp32
    gemm_f32big<1, false, true><<<dim3(DM / SBN, T_TOK / SBM), 256>>>(
        p_lnx, Wr1, nullptr, p_h, T_TOK, DM, DM);
    // 3. scores = h @ Wr2^T       — exact fp32
    gemm_f32big<1, false, false><<<dim3(DFF / SBN, T_TOK / SBM), 256>>>(
        p_h, Wr2, nullptr, p_scores, T_TOK, DFF, DM);
    // 4. top-64 per token (radix select)
    topk_kernel<<<T_TOK, 256>>>(p_scores, p_idx);
    // 5. phi + aggregate (16-row weight staging)
    phi_kernel<<<T_TOK, 256, PHI_SMEM>>>(x, W_in, nv, p_idx,
                                         pW1, pb1, pln1_g, pln1_b,
                                         pW2, pb2, pln2_g, pln2_b, p_agg);
    // 6. rho LN
    ln_kernel<<<T_TOK, 256>>>(p_agg, rln_g, rln_b, p_rln, DH);
    // 7. r = gelu(rln @ rW1 + rb1)   — exact fp32
    gemm_f32big<0, true, true><<<dim3(DM / SBN, T_TOK / SBM), 256>>>(
        p_rln, rW1, rb1, p_r, T_TOK, DM, DH);
    // 8. out = r @ rW2 + rb2         — exact fp32
    gemm_f32big<0, true, false><<<dim3(DM / SBN, T_TOK / SBM), 256>>>(
        p_r, rW2, rb2, out, T_TOK, DM, DM);
}

// round 10
// speedup vs baseline: 1.1532x; 1.1532x over previous
#include <cuda_runtime.h>
#include <math.h>

// ---------------- problem constants ----------------
#define T_TOK 4096
#define DM    512
#define DFF   2048
#define DN    128
#define DH    256
#define TK    64
#define EPSV  1e-5f

// ---------------- scratch (device globals, no allocation) ----------------
__device__ float g_lnx[T_TOK * DM];
__device__ float g_h[T_TOK * DM];
__device__ float g_scores[T_TOK * DFF];
__device__ int   g_idx[T_TOK * TK];
__device__ float g_agg[T_TOK * DH];
__device__ float g_rln[T_TOK * DH];
__device__ float g_r[T_TOK * DM];

__device__ __forceinline__ float gelu_f(float x) {
    return 0.5f * x * (1.0f + erff(x * 0.7071067811865476f));
}
__device__ __forceinline__ float to_tf32(float x) {
    float y; asm("cvt.rna.tf32.f32 %0, %1;" : "=f"(y) : "f"(x)); return y;
}
__device__ __forceinline__ void mma_tf32(float* c, const unsigned* a, const unsigned* b) {
    asm volatile("mma.sync.aligned.m16n8k8.row.col.f32.tf32.tf32.f32 "
                 "{%0,%1,%2,%3}, {%4,%5,%6,%7}, {%8,%9}, {%0,%1,%2,%3};"
                 : "+f"(c[0]), "+f"(c[1]), "+f"(c[2]), "+f"(c[3])
                 : "r"(a[0]), "r"(a[1]), "r"(a[2]), "r"(a[3]),
                   "r"(b[0]), "r"(b[1]));
}

// ---------------- LayerNorm over last dim (D = 256 or 512), block per row ----
__global__ void ln_kernel(const float* __restrict__ in, const float* __restrict__ g,
                          const float* __restrict__ b, float* __restrict__ out, int D) {
    int t = blockIdx.x, tid = threadIdx.x;
    int lane = tid & 31, wid = tid >> 5;
    __shared__ float red[8];
    __shared__ float s_mu, s_rs;
    const float* row = in + (size_t)t * D;
    float v0 = row[tid];
    float v1 = (D > 256) ? row[tid + 256] : 0.0f;
    float sum = v0 + v1;
    #pragma unroll
    for (int o = 16; o; o >>= 1) sum += __shfl_xor_sync(0xffffffffu, sum, o);
    if (lane == 0) red[wid] = sum;
    __syncthreads();
    if (tid == 0) {
        float s = 0.f;
        #pragma unroll
        for (int w = 0; w < 8; w++) s += red[w];
        s_mu = s / (float)D;
    }
    __syncthreads();
    float mu = s_mu;
    float d0 = v0 - mu, d1 = (D > 256) ? (v1 - mu) : 0.0f;
    float vs = d0 * d0 + d1 * d1;
    #pragma unroll
    for (int o = 16; o; o >>= 1) vs += __shfl_xor_sync(0xffffffffu, vs, o);
    if (lane == 0) red[wid] = vs;
    __syncthreads();
    if (tid == 0) {
        float s = 0.f;
        #pragma unroll
        for (int w = 0; w < 8; w++) s += red[w];
        s_rs = rsqrtf(s / (float)D + EPSV);
    }
    __syncthreads();
    float rs = s_rs;
    float* orow = out + (size_t)t * D;
    orow[tid] = d0 * rs * g[tid] + b[tid];
    if (D > 256) orow[tid + 256] = d1 * rs * g[tid + 256] + b[tid + 256];
}

// ---------------- scalar fp32 GEMM, 128x128 tile, 8x8/thread -----------------
// Exact fp32 (bit-identical accumulation order); register double-buffered
// staging: stage k+1 global loads issued after the stage-k barrier so fetch
// latency overlaps the FMA block.
#define SBM 128
#define SBN 128
#define SBK 16
#define SAT 132
#define SBT 132
template <int B_LAYOUT, bool HAS_BIAS, bool DO_GELU>
__global__ void __launch_bounds__(256, 2)
gemm_f32big(const float* __restrict__ A, const float* __restrict__ B,
            const float* __restrict__ bias, float* __restrict__ C,
            int M, int N, int K) {
    __shared__ float As[SBK * SAT];
    __shared__ float Bs[SBK * SBT];
    const int tid = threadIdx.x;
    const int tx = tid & 15, ty = tid >> 4;
    const int m0 = blockIdx.y * SBM, n0 = blockIdx.x * SBN;

    // thread mappings for staging
    const int ar = tid >> 1, akh = (tid & 1) * 8;              // A: [k][m]
    const int bn = tid >> 1, bkh = (tid & 1) * 8;              // B layout1
    const int bkr = tid >> 4, bnn = (tid & 15) * 8;            // B layout0

    float fa[8], fb[8];
    {   // preload k0 = 0
        const float* srcA = A + (size_t)(m0 + ar) * K + akh;
        float4 a0 = *reinterpret_cast<const float4*>(srcA);
        float4 a1 = *reinterpret_cast<const float4*>(srcA + 4);
        fa[0]=a0.x; fa[1]=a0.y; fa[2]=a0.z; fa[3]=a0.w;
        fa[4]=a1.x; fa[5]=a1.y; fa[6]=a1.z; fa[7]=a1.w;
        const float* srcB = (B_LAYOUT == 1)
            ? B + (size_t)(n0 + bn) * K + bkh
            : B + (size_t)bkr * N + n0 + bnn;
        float4 b0 = *reinterpret_cast<const float4*>(srcB);
        float4 b1 = *reinterpret_cast<const float4*>(srcB + 4);
        fb[0]=b0.x; fb[1]=b0.y; fb[2]=b0.z; fb[3]=b0.w;
        fb[4]=b1.x; fb[5]=b1.y; fb[6]=b1.z; fb[7]=b1.w;
    }

    float acc[8][8] = {};
    for (int k0 = 0; k0 < K; k0 += SBK) {
        __syncthreads();
        #pragma unroll
        for (int j = 0; j < 8; j++) As[(akh + j) * SAT + ar] = fa[j];
        if (B_LAYOUT == 1) {
            #pragma unroll
            for (int j = 0; j < 8; j++) Bs[(bkh + j) * SBT + bn] = fb[j];
        } else {
            #pragma unroll
            for (int j = 0; j < 8; j++) Bs[bkr * SBT + bnn + j] = fb[j];
        }
        __syncthreads();
        if (k0 + SBK < K) {   // prefetch next stage into registers
            int kn = k0 + SBK;
            const float* srcA = A + (size_t)(m0 + ar) * K + kn + akh;
            float4 a0 = *reinterpret_cast<const float4*>(srcA);
            float4 a1 = *reinterpret_cast<const float4*>(srcA + 4);
            fa[0]=a0.x; fa[1]=a0.y; fa[2]=a0.z; fa[3]=a0.w;
            fa[4]=a1.x; fa[5]=a1.y; fa[6]=a1.z; fa[7]=a1.w;
            const float* srcB = (B_LAYOUT == 1)
                ? B + (size_t)(n0 + bn) * K + kn + bkh
                : B + (size_t)(kn + bkr) * N + n0 + bnn;
            float4 b0 = *reinterpret_cast<const float4*>(srcB);
            float4 b1 = *reinterpret_cast<const float4*>(srcB + 4);
            fb[0]=b0.x; fb[1]=b0.y; fb[2]=b0.z; fb[3]=b0.w;
            fb[4]=b1.x; fb[5]=b1.y; fb[6]=b1.z; fb[7]=b1.w;
        }
        #pragma unroll 4
        for (int kc = 0; kc < SBK; kc++) {
            float a[8], b[8];
            float4 a0 = *reinterpret_cast<const float4*>(&As[kc * SAT + ty * 8]);
            float4 a1 = *reinterpret_cast<const float4*>(&As[kc * SAT + ty * 8 + 4]);
            float4 b0 = *reinterpret_cast<const float4*>(&Bs[kc * SBT + tx * 8]);
            float4 b1 = *reinterpret_cast<const float4*>(&Bs[kc * SBT + tx * 8 + 4]);
            a[0] = a0.x; a[1] = a0.y; a[2] = a0.z; a[3] = a0.w;
            a[4] = a1.x; a[5] = a1.y; a[6] = a1.z; a[7] = a1.w;
            b[0] = b0.x; b[1] = b0.y; b[2] = b0.z; b[3] = b0.w;
            b[4] = b1.x; b[5] = b1.y; b[6] = b1.z; b[7] = b1.w;
            #pragma unroll
            for (int i = 0; i < 8; i++)
                #pragma unroll
                for (int j = 0; j < 8; j++)
                    acc[i][j] = fmaf(a[i], b[j], acc[i][j]);
        }
    }
    #pragma unroll
    for (int i = 0; i < 8; i++) {
        int m = m0 + ty * 8 + i;
        float v[8];
        #pragma unroll
        for (int j = 0; j < 8; j++) {
            v[j] = acc[i][j];
            if (HAS_BIAS) v[j] += bias[n0 + tx * 8 + j];
            if (DO_GELU) v[j] = gelu_f(v[j]);
        }
        *reinterpret_cast<float4*>(&C[(size_t)m * N + n0 + tx * 8]) =
            make_float4(v[0], v[1], v[2], v[3]);
        *reinterpret_cast<float4*>(&C[(size_t)m * N + n0 + tx * 8 + 4]) =
            make_float4(v[4], v[5], v[6], v[7]);
    }
}

// ---------------- top-64 of 2048 via 4-pass byte radix select ----------------
__global__ void topk_kernel(const float* __restrict__ scores, int* __restrict__ idx) {
    __shared__ unsigned u_s[DFF];
    __shared__ int hist[256];
    __shared__ int cum[256];
    __shared__ unsigned s_prefix;
    __shared__ int s_krem, s_cnt, s_eqcnt;
    __shared__ int eq_idx[64];
    int t = blockIdx.x, tid = threadIdx.x;
    for (int i = tid; i < DFF; i += 256) {
        unsigned b = __float_as_uint(scores[(size_t)t * DFF + i]);
        b ^= ((unsigned)((int)b >> 31)) | 0x80000000u;
        u_s[i] = b;
    }
    if (tid == 0) { s_prefix = 0u; s_krem = TK; s_cnt = 0; s_eqcnt = 0; }
    __syncthreads();
    for (int shift = 24; shift >= 0; shift -= 8) {
        hist[tid] = 0;
        __syncthreads();
        unsigned pmask = (shift == 24) ? 0u : (0xFFFFFFFFu << (shift + 8));
        unsigned prefix = s_prefix;
        for (int i = tid; i < DFF; i += 256) {
            unsigned b = u_s[i];
            if ((b & pmask) == prefix) atomicAdd(&hist[(b >> shift) & 255], 1);
        }
        __syncthreads();
        cum[tid] = hist[tid];
        __syncthreads();
        #pragma unroll
        for (int off = 1; off < 256; off <<= 1) {
            int v = (tid + off < 256) ? cum[tid + off] : 0;
            __syncthreads();
            cum[tid] += v;
            __syncthreads();
        }
        int krem = s_krem;
        int above = (tid + 1 < 256) ? cum[tid + 1] : 0;
        if (cum[tid] >= krem && above < krem) {
            s_prefix = prefix | ((unsigned)tid << shift);
            s_krem = krem - above;
        }
        __syncthreads();
    }
    unsigned thr = s_prefix;
    int need_eq = s_krem;
    for (int i = tid; i < DFF; i += 256) {
        unsigned b = u_s[i];
        if (b > thr) {
            int p = atomicAdd(&s_cnt, 1);
            idx[(size_t)t * TK + p] = i;
        } else if (b == thr) {
            int p = atomicAdd(&s_eqcnt, 1);
            if (p < 64) eq_idx[p] = i;
        }
    }
    __syncthreads();
    if (tid == 0) {
        int n = s_eqcnt; if (n > 64) n = 64;
        for (int a = 1; a < n; a++) {
            int key = eq_idx[a]; int p = a - 1;
            while (p >= 0 && eq_idx[p] > key) { eq_idx[p + 1] = eq_idx[p]; p--; }
            eq_idx[p + 1] = key;
        }
        int base = s_cnt;
        for (int j = 0; j < need_eq; j++) idx[(size_t)t * TK + base + j] = eq_idx[j];
    }
}

// ---------------- phi: round-8 kernel + register double-buffered staging -----
// one block (256 thr = 8 warps) per token; warps tiled 2(m) x 4(n) over [64,256]
// 8-row weight stages (proven layout); stage k+1 loads overlap stage-k mma.
#define SA  140
#define SH  268
#define SWS 264
__global__ void __launch_bounds__(256, 2)
phi_kernel(const float* __restrict__ x, const float* __restrict__ W_in,
           const float* __restrict__ nv, const int* __restrict__ idx,
           const float* __restrict__ pW1, const float* __restrict__ pb1,
           const float* __restrict__ pln1_g, const float* __restrict__ pln1_b,
           const float* __restrict__ pW2, const float* __restrict__ pb2,
           const float* __restrict__ pln2_g, const float* __restrict__ pln2_b,
           float* __restrict__ agg) {
    extern __shared__ float sm[];
    float* h_s   = sm;
    float* phi_s = sm;
    float* xf_s  = sm + 64 * SH;
    float* w_s   = xf_s + 512;
    float* agg_s = w_s + 8 * SWS;
    int*   idx_s = (int*)(agg_s + 256);

    const int t = blockIdx.x, tid = threadIdx.x;
    const int lane = tid & 31, wid = tid >> 5;
    const int g = lane >> 2, tig = lane & 3;
    const int wm = wid >> 2, wn = wid & 3;
    const int sr = tid >> 5, sc0 = (tid & 31) * 8;   // staging mapping

    if (tid < TK) idx_s[tid] = idx[(size_t)t * TK + tid];
    for (int i = tid; i < DM; i += 256) xf_s[i] = x[(size_t)t * DM + i];
    agg_s[tid] = 0.0f;
    __syncthreads();

    for (int e = tid; e < TK * DN; e += 256) {
        int k = e >> 7, c = e & 127;
        phi_s[k * SA + c] = to_tf32(nv[(size_t)idx_s[k] * DN + c]);
    }
    if (tid < TK) {
        #pragma unroll
        for (int c = 129; c < 136; c++) phi_s[tid * SA + c] = 0.0f;
    }
    #pragma unroll
    for (int kr = 0; kr < 8; kr++) {
        int k = wid * 8 + kr;
        const float* wr = W_in + (size_t)idx_s[k] * DM;
        float s = 0.f;
        #pragma unroll
        for (int c = 0; c < DM / 32; c++) s = fmaf(xf_s[lane + 32 * c], wr[lane + 32 * c], s);
        #pragma unroll
        for (int o = 16; o; o >>= 1) s += __shfl_xor_sync(0xffffffffu, s, o);
        if (lane == 0) phi_s[k * SA + 128] = to_tf32(gelu_f(s));
    }

    float acc[2][8][4];
    #pragma unroll
    for (int i = 0; i < 2; i++)
        #pragma unroll
        for (int j = 0; j < 8; j++)
            #pragma unroll
            for (int q = 0; q < 4; q++) acc[i][j][q] = 0.f;

    float wv[8];
    {   // preload GEMM1 stage 0 (rows 0..7, all < 129)
        const float* src = pW1 + (size_t)sr * 256 + sc0;
        float4 p = *reinterpret_cast<const float4*>(src);
        float4 q = *reinterpret_cast<const float4*>(src + 4);
        wv[0]=p.x; wv[1]=p.y; wv[2]=p.z; wv[3]=p.w;
        wv[4]=q.x; wv[5]=q.y; wv[6]=q.z; wv[7]=q.w;
    }
    // ---- GEMM1: [64,136(pad)] @ pW1[136(pad),256], 17 stages of 8 rows ----
    for (int ks = 0; ks < 17; ks++) {
        int k0 = ks * 8;
        __syncthreads();
        #pragma unroll
        for (int i = 0; i < 8; i++) w_s[sr * SWS + sc0 + i] = to_tf32(wv[i]);
        __syncthreads();
        if (ks < 16) {   // prefetch next stage
            int grow = (ks + 1) * 8 + sr;
            if (grow < 129) {
                const float* src = pW1 + (size_t)grow * 256 + sc0;
                float4 p = *reinterpret_cast<const float4*>(src);
                float4 q = *reinterpret_cast<const float4*>(src + 4);
                wv[0]=p.x; wv[1]=p.y; wv[2]=p.z; wv[3]=p.w;
                wv[4]=q.x; wv[5]=q.y; wv[6]=q.z; wv[7]=q.w;
            } else {
                #pragma unroll
                for (int i = 0; i < 8; i++) wv[i] = 0.f;
            }
        }
        unsigned a[2][4];
        #pragma unroll
        for (int mt = 0; mt < 2; mt++) {
            const float* ap = phi_s + (size_t)(wm * 32 + mt * 16 + g) * SA + k0 + tig;
            a[mt][0] = __float_as_uint(ap[0]);
            a[mt][1] = __float_as_uint(ap[8 * SA]);
            a[mt][2] = __float_as_uint(ap[4]);
            a[mt][3] = __float_as_uint(ap[8 * SA + 4]);
        }
        #pragma unroll
        for (int nt = 0; nt < 8; nt++) {
            unsigned b[2];
            int ncol = wn * 64 + nt * 8 + g;
            b[0] = __float_as_uint(w_s[tig * SWS + ncol]);
            b[1] = __float_as_uint(w_s[(tig + 4) * SWS + ncol]);
            mma_tf32(acc[0][nt], a[0], b);
            mma_tf32(acc[1][nt], a[1], b);
        }
    }
    __syncthreads();   // phi_s dead; safe to overwrite with h
    #pragma unroll
    for (int mt = 0; mt < 2; mt++) {
        int row = wm * 32 + mt * 16 + g;
        #pragma unroll
        for (int nt = 0; nt < 8; nt++) {
            int col = wn * 64 + nt * 8 + tig * 2;
            h_s[row * SH + col]           = acc[mt][nt][0];
            h_s[row * SH + col + 1]       = acc[mt][nt][1];
            h_s[(row + 8) * SH + col]     = acc[mt][nt][2];
            h_s[(row + 8) * SH + col + 1] = acc[mt][nt][3];
        }
    }
    __syncthreads();
    // ---- bias + LN1 + GELU (fp32), store back tf32 ----
    {
        float gg[8], bb[8], pb[8];
        #pragma unroll
        for (int q = 0; q < 8; q++) {
            int j = lane + 32 * q;
            gg[q] = pln1_g[j]; bb[q] = pln1_b[j]; pb[q] = pb1[j];
        }
        #pragma unroll
        for (int kr = 0; kr < 8; kr++) {
            int r = wid * 8 + kr;
            float v[8]; float sum = 0.f;
            #pragma unroll
            for (int q = 0; q < 8; q++) { v[q] = h_s[r * SH + lane + 32 * q] + pb[q]; sum += v[q]; }
            #pragma unroll
            for (int o = 16; o; o >>= 1) sum += __shfl_xor_sync(0xffffffffu, sum, o);
            float mu = sum * (1.f / 256.f);
            float vs = 0.f;
            #pragma unroll
            for (int q = 0; q < 8; q++) { float d = v[q] - mu; vs = fmaf(d, d, vs); }
            #pragma unroll
            for (int o = 16; o; o >>= 1) vs += __shfl_xor_sync(0xffffffffu, vs, o);
            float rs = rsqrtf(vs * (1.f / 256.f) + EPSV);
            #pragma unroll
            for (int q = 0; q < 8; q++)
                h_s[r * SH + lane + 32 * q] = to_tf32(gelu_f((v[q] - mu) * rs * gg[q] + bb[q]));
        }
    }

    // ---- GEMM2: [64,256] @ pW2[256,256], 32 stages of 8 rows ----
    #pragma unroll
    for (int i = 0; i < 2; i++)
        #pragma unroll
        for (int j = 0; j < 8; j++)
            #pragma unroll
            for (int q = 0; q < 4; q++) acc[i][j][q] = 0.f;
    {   // preload GEMM2 stage 0
        const float* src = pW2 + (size_t)sr * 256 + sc0;
        float4 p = *reinterpret_cast<const float4*>(src);
        float4 q = *reinterpret_cast<const float4*>(src + 4);
        wv[0]=p.x; wv[1]=p.y; wv[2]=p.z; wv[3]=p.w;
        wv[4]=q.x; wv[5]=q.y; wv[6]=q.z; wv[7]=q.w;
    }
    for (int ks = 0; ks < 32; ks++) {
        int k0 = ks * 8;
        __syncthreads();
        #pragma unroll
        for (int i = 0; i < 8; i++) w_s[sr * SWS + sc0 + i] = to_tf32(wv[i]);
        __syncthreads();
        if (ks < 31) {   // prefetch next stage (rows always < 256)
            const float* src = pW2 + (size_t)((ks + 1) * 8 + sr) * 256 + sc0;
            float4 p = *reinterpret_cast<const float4*>(src);
            float4 q = *reinterpret_cast<const float4*>(src + 4);
            wv[0]=p.x; wv[1]=p.y; wv[2]=p.z; wv[3]=p.w;
            wv[4]=q.x; wv[5]=q.y; wv[6]=q.z; wv[7]=q.w;
        }
        unsigned a[2][4];
        #pragma unroll
        for (int mt = 0; mt < 2; mt++) {
            const float* ap = h_s + (size_t)(wm * 32 + mt * 16 + g) * SH + k0 + tig;
            a[mt][0] = __float_as_uint(ap[0]);
            a[mt][1] = __float_as_uint(ap[8 * SH]);
            a[mt][2] = __float_as_uint(ap[4]);
            a[mt][3] = __float_as_uint(ap[8 * SH + 4]);
        }
        #pragma unroll
        for (int nt = 0; nt < 8; nt++) {
            unsigned b[2];
            int ncol = wn * 64 + nt * 8 + g;
            b[0] = __float_as_uint(w_s[tig * SWS + ncol]);
            b[1] = __float_as_uint(w_s[(tig + 4) * SWS + ncol]);
            mma_tf32(acc[0][nt], a[0], b);
            mma_tf32(acc[1][nt], a[1], b);
        }
    }
    __syncthreads();
    #pragma unroll
    for (int mt = 0; mt < 2; mt++) {
        int row = wm * 32 + mt * 16 + g;
        #pragma unroll
        for (int nt = 0; nt < 8; nt++) {
            int col = wn * 64 + nt * 8 + tig * 2;
            h_s[row * SH + col]           = acc[mt][nt][0];
            h_s[row * SH + col + 1]       = acc[mt][nt][1];
            h_s[(row + 8) * SH + col]     = acc[mt][nt][2];
            h_s[(row + 8) * SH + col + 1] = acc[mt][nt][3];
        }
    }
    __syncthreads();
    // ---- bias + LN2 + sum over K ----
    {
        float gg[8], bb[8], pb[8], aw[8];
        #pragma unroll
        for (int q = 0; q < 8; q++) {
            int j = lane + 32 * q;
            gg[q] = pln2_g[j]; bb[q] = pln2_b[j]; pb[q] = pb2[j]; aw[q] = 0.f;
        }
        #pragma unroll
        for (int kr = 0; kr < 8; kr++) {
            int r = wid * 8 + kr;
            float v[8]; float sum = 0.f;
            #pragma unroll
            for (int q = 0; q < 8; q++) { v[q] = h_s[r * SH + lane + 32 * q] + pb[q]; sum += v[q]; }
            #pragma unroll
            for (int o = 16; o; o >>= 1) sum += __shfl_xor_sync(0xffffffffu, sum, o);
            float mu = sum * (1.f / 256.f);
            float vs = 0.f;
            #pragma unroll
            for (int q = 0; q < 8; q++) { float d = v[q] - mu; vs = fmaf(d, d, vs); }
            #pragma unroll
            for (int o = 16; o; o >>= 1) vs += __shfl_xor_sync(0xffffffffu, vs, o);
            float rs = rsqrtf(vs * (1.f / 256.f) + EPSV);
            #pragma unroll
            for (int q = 0; q < 8; q++)
                aw[q] += (v[q] - mu) * rs * gg[q] + bb[q];
        }
        #pragma unroll
        for (int q = 0; q < 8; q++) atomicAdd(&agg_s[lane + 32 * q], aw[q]);
    }
    __syncthreads();
    agg[(size_t)t * DH + tid] = agg_s[tid];
}

// ---------------- host launcher ----------------
extern "C" void kernel_launch(void* const* d_in, const int* in_sizes, int n_in,
                              void* d_out, int out_size) {
    const float* x      = (const float*)d_in[0];
    const float* W_in   = (const float*)d_in[1];
    const float* nv     = (const float*)d_in[2];
    const float* Wr1    = (const float*)d_in[3];
    const float* Wr2    = (const float*)d_in[4];
    const float* rn_g   = (const float*)d_in[5];
    const float* rn_b   = (const float*)d_in[6];
    const float* pW1    = (const float*)d_in[7];
    const float* pb1    = (const float*)d_in[8];
    const float* pln1_g = (const float*)d_in[9];
    const float* pln1_b = (const float*)d_in[10];
    const float* pW2    = (const float*)d_in[11];
    const float* pb2    = (const float*)d_in[12];
    const float* pln2_g = (const float*)d_in[13];
    const float* pln2_b = (const float*)d_in[14];
    const float* rln_g  = (const float*)d_in[15];
    const float* rln_b  = (const float*)d_in[16];
    const float* rW1    = (const float*)d_in[17];
    const float* rb1    = (const float*)d_in[18];
    const float* rW2    = (const float*)d_in[19];
    const float* rb2    = (const float*)d_in[20];
    float* out = (float*)d_out;

    float *p_lnx, *p_h, *p_scores, *p_agg, *p_rln, *p_r; int* p_idx;
    cudaGetSymbolAddress((void**)&p_lnx, g_lnx);
    cudaGetSymbolAddress((void**)&p_h, g_h);
    cudaGetSymbolAddress((void**)&p_scores, g_scores);
    cudaGetSymbolAddress((void**)&p_idx, g_idx);
    cudaGetSymbolAddress((void**)&p_agg, g_agg);
    cudaGetSymbolAddress((void**)&p_rln, g_rln);
    cudaGetSymbolAddress((void**)&p_r, g_r);

    const int PHI_SMEM = (64 * SH + 512 + 8 * SWS + 256) * 4 + TK * 4;
    cudaFuncSetAttribute(phi_kernel, cudaFuncAttributeMaxDynamicSharedMemorySize, PHI_SMEM);

    // 1. router LN (fp32 exact)
    ln_kernel<<<T_TOK, 256>>>(x, rn_g, rn_b, p_lnx, DM);
    // 2. h = gelu(ln_x @ Wr1^T)   — exact fp32
    gemm_f32big<1, false, true><<<dim3(DM / SBN, T_TOK / SBM), 256>>>(
        p_lnx, Wr1, nullptr, p_h, T_TOK, DM, DM);
    // 3. scores = h @ Wr2^T       — exact fp32
    gemm_f32big<1, false, false><<<dim3(DFF / SBN, T_TOK / SBM), 256>>>(
        p_h, Wr2, nullptr, p_scores, T_TOK, DFF, DM);
    // 4. top-64 per token (radix select)
    topk_kernel<<<T_TOK, 256>>>(p_scores, p_idx);
    // 5. phi + aggregate (8-row staging + register double-buffer)
    phi_kernel<<<T_TOK, 256, PHI_SMEM>>>(x, W_in, nv, p_idx,
                                         pW1, pb1, pln1_g, pln1_b,
                                         pW2, pb2, pln2_g, pln2_b, p_agg);
    // 6. rho LN
    ln_kernel<<<T_TOK, 256>>>(p_agg, rln_g, rln_b, p_rln, DH);
    // 7. r = gelu(rln @ rW1 + rb1)   — exact fp32
    gemm_f32big<0, true, true><<<dim3(DM / SBN, T_TOK / SBM), 256>>>(
        p_rln, rW1, rb1, p_r, T_TOK, DM, DH);
    // 8. out = r @ rW2 + rb2         — exact fp32
    gemm_f32big<0, true, false><<<dim3(DM / SBN, T_TOK / SBM), 256>>>(
        p_r, rW2, rb2, out, T_TOK, DM, DM);
}